// round 11
// baseline (speedup 1.0000x reference)
#include <cuda_runtime.h>
#include <cstdint>

// SignalDualBackground: out[b,c,s,t] = (1 - spikes[b,c,s,t]) * stat[b,c,t]
//   x[b,c,t]  = mean_s spikes[b,c,s,t]            (S=64)
//   stat[.,t] = beta*stat[.,t-1] + (1-beta)*x[.,t], stat[.,-1]=0  (T=1024)
//
// R11 = R7's tile-sharing pair (ideal 1.02GB traffic) WITHOUT clusters:
// CTA pair (2k, 2k+1) shares tile k (32 rows each). The partial-sum
// exchange goes through __device__ L2 scratch with per-column
// release/acquire flags (consumer resets -> replay-safe), instead of
// DSMEM + barrier.cluster. This removes the paired-SM barrier coupling
// that synchronized bubbles chip-wide (R7 busy 75.6% vs R5's 78.6%).
// Only the 8 scan warps wait (nanosleep backoff); parts 1-3 go straight
// to barrier B. Pairs are adjacent -> co-resident -> exchange is L2-hit.

#define T_DIM 1024
#define S_DIM 64
#define THREADS 1024
#define T4 (T_DIM / 4)              // 256 float4 per row
#define ROWS_PER_CTA 32
#define ROWS_PER_THREAD 8           // 32 rows / 4 parts
#define TILE_F4 (S_DIM * T4)        // 16384 float4 per tile
#define MAX_TILES 2048

// L2 exchange scratch (zero-initialized at load; flags restored to 0 by
// the consumer each launch -> graph-replay safe).
__device__ float4   g_xsum[MAX_TILES * 2 * T4];   // 16MB
__device__ unsigned g_flag[MAX_TILES * 2 * T4];   // 4MB

__global__ __launch_bounds__(THREADS, 2)
void sdb_kernel(const float4* __restrict__ sp,
                const float* __restrict__ beta_p,
                float4* __restrict__ out) {
    __shared__ float4 red[THREADS];   // 16KB: per-thread partials
    __shared__ float4 statS[T4];      // 4KB: broadcast stat
    __shared__ float Ms[8], As[8];

    const int tid  = threadIdx.x;
    const int col  = tid & (T4 - 1);  // 0..255 time chunk
    const int part = tid >> 8;        // 0..3
    const int lane = tid & 31;
    const int wid  = tid >> 5;        // part0 -> 0..7

    const int rank = (int)(blockIdx.x & 1);      // 0/1 within pair
    const int tile = (int)(blockIdx.x >> 1);
    const size_t base = (size_t)tile * TILE_F4;
    const int srow0 = rank * ROWS_PER_CTA + part * ROWS_PER_THREAD;

    const float beta = beta_p[0];
    const float omb  = 1.0f - beta;

    // ---------- Phase 1: partial sums over this CTA's 8 rows/thread ----------
    const float4* p = sp + base + (size_t)srow0 * T4 + col;
    float4 acc0 = make_float4(0.f, 0.f, 0.f, 0.f);
    float4 acc1 = make_float4(0.f, 0.f, 0.f, 0.f);
    #pragma unroll
    for (int k = 0; k < ROWS_PER_THREAD; k += 2) {
        float4 v0 = p[(size_t)k * T4];
        float4 v1 = p[(size_t)(k + 1) * T4];
        acc0.x += v0.x; acc0.y += v0.y; acc0.z += v0.z; acc0.w += v0.w;
        acc1.x += v1.x; acc1.y += v1.y; acc1.z += v1.z; acc1.w += v1.w;
    }
    acc0.x += acc1.x; acc0.y += acc1.y; acc0.z += acc1.z; acc0.w += acc1.w;
    red[tid] = acc0;
    __syncthreads();                  // barrier A

    // ---------- Phase 2: part 0 exchanges partials via L2 and scans ----------
    if (part == 0) {
        float4 a4 = red[col];
        float4 b4 = red[col + 256];
        float4 c4 = red[col + 512];
        float4 d4 = red[col + 768];
        float4 csum;
        csum.x = a4.x + b4.x + c4.x + d4.x;
        csum.y = a4.y + b4.y + c4.y + d4.y;
        csum.z = a4.z + b4.z + c4.z + d4.z;
        csum.w = a4.w + b4.w + c4.w + d4.w;

        // publish my CTA's column sums (release flag orders the data)
        const int my = (tile * 2 + rank) * T4 + col;
        __stcg(&g_xsum[my], csum);
        asm volatile("st.global.release.gpu.u32 [%0], %1;"
                     :: "l"(&g_flag[my]), "r"(1u) : "memory");

        // consume the peer CTA's column sums
        const int pe = (tile * 2 + (rank ^ 1)) * T4 + col;
        unsigned f;
        while (true) {
            asm volatile("ld.global.acquire.gpu.u32 %0, [%1];"
                         : "=r"(f) : "l"(&g_flag[pe]) : "memory");
            if (f) break;
            __nanosleep(64);
        }
        float4 o4 = __ldcg(&g_xsum[pe]);
        // consumer resets the flag -> next launch starts clean
        asm volatile("st.global.relaxed.gpu.u32 [%0], %1;"
                     :: "l"(&g_flag[pe]), "r"(0u) : "memory");

        const float inv = 1.0f / (float)S_DIM;
        const float x0 = (csum.x + o4.x) * inv;
        const float x1 = (csum.y + o4.y) * inv;
        const float x2 = (csum.z + o4.z) * inv;
        const float x3 = (csum.w + o4.w) * inv;

        // per-thread composite over 4 time steps: state' = m*state + a
        float a = omb * x0;
        a = beta * a + omb * x1;
        a = beta * a + omb * x2;
        a = beta * a + omb * x3;
        float m = beta * beta;
        m = m * m;                    // beta^4

        #pragma unroll
        for (int d = 1; d < 32; d <<= 1) {
            float ap = __shfl_up_sync(0xffffffffu, a, d);
            float mp = __shfl_up_sync(0xffffffffu, m, d);
            if (lane >= d) { a += m * ap; m *= mp; }
        }
        if (lane == 31) { Ms[wid] = m; As[wid] = a; }
        asm volatile("bar.sync 1, 256;" ::: "memory");  // 8 scan warps only

        float pref = 0.0f;
        #pragma unroll
        for (int w = 0; w < 8; ++w) {
            if (w == wid) break;
            pref = Ms[w] * pref + As[w];
        }
        const float a_full = a + m * pref;
        const float a_prev = __shfl_up_sync(0xffffffffu, a_full, 1);
        const float a_excl = (lane > 0) ? a_prev : pref;

        float st = a_excl;
        st = beta * st + omb * x0; const float r0 = st;
        st = beta * st + omb * x1; const float r1 = st;
        st = beta * st + omb * x2; const float r2 = st;
        st = beta * st + omb * x3; const float r3 = st;
        statS[col] = make_float4(r0, r1, r2, r3);
    }
    __syncthreads();                  // barrier B: stat visible to all warps

    // ---------- Phase 3: out = (1-spike)*stat ; re-read hits L2 ----------
    const float4 st4 = statS[col];
    float4* pw = out + base + (size_t)srow0 * T4 + col;
    #pragma unroll
    for (int k = 0; k < ROWS_PER_THREAD; ++k) {
        float4 v = __ldcs(&p[(size_t)k * T4]);   // last use: evict-first
        float4 o;
        o.x = (1.0f - v.x) * st4.x;
        o.y = (1.0f - v.y) * st4.y;
        o.z = (1.0f - v.z) * st4.z;
        o.w = (1.0f - v.w) * st4.w;
        __stcs(&pw[(size_t)k * T4], o);           // streaming store
    }
}

extern "C" void kernel_launch(void* const* d_in, const int* in_sizes, int n_in,
                              void* d_out, int out_size) {
    const float* spikes = (const float*)d_in[0];
    const float* beta   = (const float*)d_in[1];
    float* out          = (float*)d_out;

    const int nbc = in_sizes[0] / (S_DIM * T_DIM);  // 2048 tiles

    // adjacent CTA pair (2k, 2k+1) shares tile k -> co-resident, L2 exchange
    sdb_kernel<<<nbc * 2, THREADS>>>(
        (const float4*)spikes, beta, (float4*)out);
}

// round 12
// speedup vs baseline: 1.0716x; 1.0716x over previous
#include <cuda_runtime.h>
#include <cstdint>

// SignalDualBackground: out[b,c,s,t] = (1 - spikes[b,c,s,t]) * stat[b,c,t]
//   x[b,c,t]  = mean_s spikes[b,c,s,t]            (S=64)
//   stat[.,t] = beta*stat[.,t-1] + (1-beta)*x[.,t], stat[.,-1]=0  (T=1024)
//
// R12: TIME-SPLIT tile pair. CTA pair (2k,2k+1) shares tile k; rank r owns
// time cols [r*512, r*512+512) x all 64 synapse rows (128KB half).
//  - mean over synapses is fully CTA-local (no cross-CTA exchange!)
//  - scan: rank0's zero-init local scan is exact; it publishes ONE scalar
//    (final state s_511) via L2 release-store+flag. rank1 scans zero-init
//    in parallel, then corrects s_t += beta^(t+1) * s_511 using the
//    multiplier m_excl = beta^(4c) already produced by the (m,a) scan.
//  - rank0 never waits; rank1 waits on one flag (1 thread spins, smem
//    broadcast). Consumer resets the flag -> graph-replay safe.
// Traffic stays ideal (~1.02GB); tile footprint 38MB -> phase-3 L2 hit.

#define T_DIM 1024
#define S_DIM 64
#define THREADS 1024
#define T4 (T_DIM / 4)             // 256 float4 per full row
#define HALF_COLS 128              // float4 cols per CTA (512 time steps)
#define ROWS_PER_PART 8            // 64 rows / 8 parts
#define TILE_F4 (S_DIM * T4)       // 16384 float4 per tile
#define MAX_TILES 4096

// L2 handshake scratch (one scalar + one flag per tile). Flags are
// zero-initialized at load and reset by the consumer each launch.
__device__ float    g_state[MAX_TILES];
__device__ unsigned g_flag[MAX_TILES];

__global__ __launch_bounds__(THREADS, 2)
void sdb_kernel(const float4* __restrict__ sp,
                const float* __restrict__ beta_p,
                float4* __restrict__ out) {
    __shared__ float4 red[THREADS];     // 16KB: per-thread partials
    __shared__ float4 statS[HALF_COLS]; // 2KB: broadcast stat (this half)
    __shared__ float Ms[4], As[4];      // 4 scan-warp aggregates
    __shared__ float stateSh;           // rank1: received seed

    const int tid  = threadIdx.x;
    const int col  = tid & (HALF_COLS - 1);  // 0..127 time chunk (local)
    const int part = tid >> 7;               // 0..7 synapse partition
    const int lane = tid & 31;
    const int wid  = tid >> 5;                // part0 -> warps 0..3

    const int rank = (int)(blockIdx.x & 1);
    const int tile = (int)(blockIdx.x >> 1);
    // base points at this CTA's half: tile start + rank*128 float4 cols
    const size_t base = (size_t)tile * TILE_F4 + (size_t)rank * HALF_COLS;
    const int srow0 = part * ROWS_PER_PART;

    const float beta = beta_p[0];
    const float omb  = 1.0f - beta;
    const float b2 = beta * beta;
    const float b3 = b2 * beta;
    const float b4 = b2 * b2;

    // ---------- Phase 1: partial sums over 8 rows/thread (local cols) ----------
    const float4* p = sp + base + (size_t)srow0 * T4 + col;
    float4 acc0 = make_float4(0.f, 0.f, 0.f, 0.f);
    float4 acc1 = make_float4(0.f, 0.f, 0.f, 0.f);
    #pragma unroll
    for (int k = 0; k < ROWS_PER_PART; k += 2) {
        float4 v0 = p[(size_t)k * T4];
        float4 v1 = p[(size_t)(k + 1) * T4];
        acc0.x += v0.x; acc0.y += v0.y; acc0.z += v0.z; acc0.w += v0.w;
        acc1.x += v1.x; acc1.y += v1.y; acc1.z += v1.z; acc1.w += v1.w;
    }
    acc0.x += acc1.x; acc0.y += acc1.y; acc0.z += acc1.z; acc0.w += acc1.w;
    red[tid] = acc0;
    __syncthreads();                    // barrier A

    // ---------- Phase 2: part 0 (128 thr, 4 warps) reduces + scans ----------
    if (part == 0) {
        float4 s = red[col];
        #pragma unroll
        for (int w = 1; w < 8; ++w) {
            float4 t = red[col + w * HALF_COLS];
            s.x += t.x; s.y += t.y; s.z += t.z; s.w += t.w;
        }
        const float inv = 1.0f / (float)S_DIM;
        const float x0 = s.x * inv, x1 = s.y * inv;
        const float x2 = s.z * inv, x3 = s.w * inv;

        // zero-init local scan: per-thread composite state' = m*state + a
        float a = omb * x0;
        a = beta * a + omb * x1;
        a = beta * a + omb * x2;
        a = beta * a + omb * x3;
        float m = b4;

        #pragma unroll
        for (int d = 1; d < 32; d <<= 1) {
            float ap = __shfl_up_sync(0xffffffffu, a, d);
            float mp = __shfl_up_sync(0xffffffffu, m, d);
            if (lane >= d) { a += m * ap; m *= mp; }
        }
        if (lane == 31) { Ms[wid] = m; As[wid] = a; }
        asm volatile("bar.sync 1, 128;" ::: "memory");  // 4 scan warps only

        float prefA = 0.0f, prefM = 1.0f;
        #pragma unroll
        for (int w = 0; w < 4; ++w) {
            if (w == wid) break;
            prefA = Ms[w] * prefA + As[w];
            prefM *= Ms[w];
        }
        const float a_full = a + m * prefA;
        const float m_full = m * prefM;
        const float a_prev = __shfl_up_sync(0xffffffffu, a_full, 1);
        const float m_prev = __shfl_up_sync(0xffffffffu, m_full, 1);
        const float a_excl = (lane > 0) ? a_prev : prefA;
        const float m_excl = (lane > 0) ? m_prev : prefM;  // beta^(4c)

        float st = a_excl;
        st = beta * st + omb * x0; float r0 = st;
        st = beta * st + omb * x1; float r1 = st;
        st = beta * st + omb * x2; float r2 = st;
        st = beta * st + omb * x3; float r3 = st;

        if (rank == 0) {
            // zero-init scan IS the answer for the first half
            statS[col] = make_float4(r0, r1, r2, r3);
            if (col == HALF_COLS - 1) {
                // publish final state s_511 (release orders data before flag)
                __stcg(&g_state[tile], r3);
                asm volatile("st.global.release.gpu.u32 [%0], %1;"
                             :: "l"(&g_flag[tile]), "r"(1u) : "memory");
            }
        } else {
            // wait for rank0's seed (one thread spins, then broadcast)
            if (col == 0) {
                unsigned f;
                while (true) {
                    asm volatile("ld.global.acquire.gpu.u32 %0, [%1];"
                                 : "=r"(f) : "l"(&g_flag[tile]) : "memory");
                    if (f) break;
                    __nanosleep(32);
                }
                stateSh = __ldcg(&g_state[tile]);
                // consumer resets -> next graph replay starts clean
                asm volatile("st.global.relaxed.gpu.u32 [%0], %1;"
                             :: "l"(&g_flag[tile]), "r"(0u) : "memory");
            }
            asm volatile("bar.sync 1, 128;" ::: "memory");
            const float c0 = m_excl * stateSh;  // beta^(4c) * s_511
            r0 += c0 * beta;
            r1 += c0 * b2;
            r2 += c0 * b3;
            r3 += c0 * b4;
            statS[col] = make_float4(r0, r1, r2, r3);
        }
    }
    __syncthreads();                    // barrier B: stat visible to all

    // ---------- Phase 3: out = (1-spike)*stat ; re-read hits L2 ----------
    const float4 st4 = statS[col];
    float4* pw = out + base + (size_t)srow0 * T4 + col;
    #pragma unroll
    for (int k = 0; k < ROWS_PER_PART; ++k) {
        float4 v = __ldcs(&p[(size_t)k * T4]);   // last use: evict-first
        float4 o;
        o.x = (1.0f - v.x) * st4.x;
        o.y = (1.0f - v.y) * st4.y;
        o.z = (1.0f - v.z) * st4.z;
        o.w = (1.0f - v.w) * st4.w;
        __stcs(&pw[(size_t)k * T4], o);           // streaming store
    }
}

extern "C" void kernel_launch(void* const* d_in, const int* in_sizes, int n_in,
                              void* d_out, int out_size) {
    const float* spikes = (const float*)d_in[0];
    const float* beta   = (const float*)d_in[1];
    float* out          = (float*)d_out;

    const int nbc = in_sizes[0] / (S_DIM * T_DIM);  // 2048 tiles

    // adjacent CTA pair (2k, 2k+1) shares tile k (time-split halves)
    sdb_kernel<<<nbc * 2, THREADS>>>(
        (const float4*)spikes, beta, (float4*)out);
}